// round 15
// baseline (speedup 1.0000x reference)
#include <cuda_runtime.h>
#include <cuda_fp16.h>
#include <cstdint>

#define HW 512
#define LPATCH 4096

// ---------------- scratch ----------------
__device__ float d_M[64 * 64];
__device__ float d_wc[3 * 81];
__device__ float d_Wr[9 * 3 * 49];
__device__ float d_beta[9];
__device__ float d_bc;
__device__ float d_delta[4][4][512];
__device__ __align__(256) __half d_uimg[(size_t)4 * 4096 * 64];
__device__ __align__(256) __half d_ufea[(size_t)4 * 4096 * 64];

// ---------------- k0: compose weights, one WARP per output ----------------
__global__ void __launch_bounds__(256) k0_compose(
    const float* __restrict__ w1l, const float* __restrict__ w2l,
    const float* __restrict__ wi1, const float* __restrict__ bi1,
    const float* __restrict__ wi2, const float* __restrict__ bi2) {
    int w = (blockIdx.x * 256 + threadIdx.x) >> 5;
    int lane = threadIdx.x & 31;
    float sum = 0.f;
    if (w < 4096) {
        int i = w >> 6, j = w & 63;
#pragma unroll
        for (int k = lane; k < 128; k += 32) sum += w2l[i * 128 + k] * w1l[k * 64 + j];
#pragma unroll
        for (int o = 16; o; o >>= 1) sum += __shfl_xor_sync(0xFFFFFFFFu, sum, o);
        if (lane == 0) d_M[w] = sum;
    } else if (w < 4096 + 243) {
        int o = w - 4096;
        int c = o / 81, s = o % 81, sy = s / 9, sx = s % 9;
#pragma unroll
        for (int ry = 0; ry < 3; ry++)
#pragma unroll
            for (int rx = 0; rx < 3; rx++) {
                int qy = sy - ry, qx = sx - rx;
                if (qy < 0 || qy > 6 || qx < 0 || qx > 6) continue;
                for (int m = lane; m < 64; m += 32)
                    sum += wi2[m * 9 + ry * 3 + rx] * wi1[(m * 3 + c) * 49 + qy * 7 + qx];
            }
#pragma unroll
        for (int o2 = 16; o2; o2 >>= 1) sum += __shfl_xor_sync(0xFFFFFFFFu, sum, o2);
        if (lane == 0) d_wc[o] = sum;
    } else if (w < 4096 + 243 + 1323) {
        int o = w - 4096 - 243;
        int r = o / 147, rem = o % 147, c = rem / 49, q = rem % 49;
        for (int m = lane; m < 64; m += 32)
            sum += wi2[m * 9 + r] * wi1[(m * 3 + c) * 49 + q];
#pragma unroll
        for (int o2 = 16; o2; o2 >>= 1) sum += __shfl_xor_sync(0xFFFFFFFFu, sum, o2);
        if (lane == 0) d_Wr[o] = sum;
    } else if (w == 4096 + 243 + 1323) {
#pragma unroll
        for (int r = 0; r < 9; r++) {
            float s2 = 0.f;
            for (int m = lane; m < 64; m += 32) s2 += wi2[m * 9 + r] * bi1[m];
#pragma unroll
            for (int o2 = 16; o2; o2 >>= 1) s2 += __shfl_xor_sync(0xFFFFFFFFu, s2, o2);
            if (lane == 0) d_beta[r] = s2;
        }
    } else if (w == 4096 + 243 + 1323 + 1) {
        float s2 = 0.f;
        for (int m = lane; m < 64; m += 32) {
            float sw = 0.f;
#pragma unroll
            for (int r = 0; r < 9; r++) sw += wi2[m * 9 + r];
            s2 += bi1[m] * sw;
        }
#pragma unroll
        for (int o2 = 16; o2; o2 >>= 1) s2 += __shfl_xor_sync(0xFFFFFFFFu, s2, o2);
        if (lane == 0) d_bc = s2 + bi2[0];
    }
}

// ---------------- k1b: border deltas, one WARP per border pixel ----------------
__global__ void __launch_bounds__(256) k1b_border(const float* __restrict__ x) {
    int wid_g = (blockIdx.x * 256 + threadIdx.x) >> 5;
    int lane = threadIdx.x & 31;
    int b = wid_g >> 11, rem = wid_g & 2047, edge = rem >> 9, idx = rem & 511;
    int oy, ox;
    if (edge == 0) { oy = 0;   ox = idx; }
    else if (edge == 1) { oy = 511; ox = idx; }
    else if (edge == 2) { oy = idx; ox = 0; }
    else { oy = idx; ox = 511; }
    const float* xb = x + (size_t)b * 3 * HW * HW;
    float sum = 0.f;
#pragma unroll
    for (int ry = 0; ry < 3; ry++)
#pragma unroll
        for (int rx = 0; rx < 3; rx++) {
            int py = oy + ry - 1, px = ox + rx - 1;
            if (py >= 0 && py < HW && px >= 0 && px < HW) continue;
            int r = ry * 3 + rx;
            if (lane == 0) sum += d_beta[r];
            for (int e = lane; e < 147; e += 32) {
                int c = e / 49, q = e % 49, qy = q / 7, qx = q % 7;
                int gy = py + qy - 3, gx = px + qx - 3;
                if (gy >= 0 && gy < HW && gx >= 0 && gx < HW)
                    sum += d_Wr[(r * 3 + c) * 49 + q] * xb[c * HW * HW + gy * HW + gx];
            }
        }
#pragma unroll
    for (int o = 16; o; o >>= 1) sum += __shfl_xor_sync(0xFFFFFFFFu, sum, o);
    if (lane == 0) d_delta[b][edge][idx] = -sum;
}

// ---------------- helpers ----------------
__device__ __forceinline__ uint32_t cvta_smem(const void* p) {
    uint32_t a;
    asm("{ .reg .u64 t; cvta.to.shared.u64 t, %1; cvt.u32.u64 %0, t; }" : "=r"(a) : "l"(p));
    return a;
}
__device__ __forceinline__ void cp16(uint32_t dst, const void* src) {
    asm volatile("cp.async.cg.shared.global [%0], [%1], 16;" :: "r"(dst), "l"(src));
}

// ---------------- k1 body (conv path) ----------------
__device__ void k1_body(const float* __restrict__ x, int bid, float* sm) {
    float* sxc = sm;
    float* swc = sm + 2880;
    float* sM  = sm + 2880 + 256;
    float* sv  = sm + 2880 + 256 + 4160;
    int t = threadIdx.x;
    int xg = bid & 7, yg = (bid >> 3) & 15, b = bid >> 7;
    int ix0 = xg * 64, iy0 = yg * 32;
    const float* xb = x + (size_t)b * 3 * HW * HW;

    for (int i = t; i < 3 * 81; i += 256) swc[i] = d_wc[i];
    for (int i = t; i < 64 * 64; i += 256) sM[(i >> 6) * 65 + (i & 63)] = d_M[i];

    int col = t & 63, rg = t >> 6;
    float acc[8];
    float bias = d_bc;
#pragma unroll
    for (int j = 0; j < 8; j++) acc[j] = bias;

    for (int c = 0; c < 3; c++) {
        __syncthreads();
        for (int i = t; i < 2880; i += 256) {
            int r = i / 72, cc = i % 72;
            int gy = iy0 - 4 + r, gx = ix0 - 4 + cc;
            sxc[i] = (gy >= 0 && gy < HW && gx >= 0 && gx < HW) ? xb[c * HW * HW + gy * HW + gx] : 0.f;
        }
        __syncthreads();
#pragma unroll
        for (int dx = 0; dx < 9; dx++) {
            float win[16];
#pragma unroll
            for (int u = 0; u < 16; u++) win[u] = sxc[(rg * 8 + u) * 72 + col + dx];
#pragma unroll
            for (int dy = 0; dy < 9; dy++) {
                float w = swc[c * 81 + dy * 9 + dx];
#pragma unroll
                for (int j = 0; j < 8; j++) acc[j] += w * win[j + dy];
            }
        }
    }

    int oybase = iy0 + rg * 8;
    int ox = ix0 + col;
#pragma unroll
    for (int j = 0; j < 8; j++) {
        int oy = oybase + j;
        float a = acc[j];
        if (oy == 0) a += d_delta[b][0][ox];
        if (oy == 511) a += d_delta[b][1][ox];
        if (ox == 0 && oy > 0 && oy < 511) a += d_delta[b][2][oy];
        if (ox == 511 && oy > 0 && oy < 511) a += d_delta[b][3][oy];
        sv[(rg * 8 + (col >> 3)) * 65 + j * 8 + (col & 7)] = a;
    }
    __syncthreads();

    int i = t & 63, pb = t >> 6;
    float s[8];
#pragma unroll
    for (int kk = 0; kk < 8; kk++) s[kk] = 0.f;
    for (int j = 0; j < 64; j++) {
        float mv = sM[i * 65 + j];
#pragma unroll
        for (int kk = 0; kk < 8; kk++) s[kk] += mv * sv[(pb + 4 * kk) * 65 + j];
    }
    int prow0 = iy0 >> 3, pcol0 = ix0 >> 3;
#pragma unroll
    for (int kk = 0; kk < 8; kk++) {
        int p = pb + 4 * kk;
        int l = (prow0 + (p >> 3)) * 64 + pcol0 + (p & 7);
        d_uimg[((size_t)b * LPATCH + l) * 64 + i] = __float2half_rn(fmaxf(s[kk], 0.f));
    }
}

// ---------------- k2 body (fea path) ----------------
__device__ void k2_body(const float* __restrict__ fea, const float* __restrict__ wfea,
                        const float* __restrict__ bfea, int bid, float* sm) {
    float* buf = sm;
    float* sM  = sm + 8192;
    float* sv  = sm + 8192 + 4160;
    float* swf = sm + 8192 + 4160 + 1040;
    int t = threadIdx.x;
    int xg = bid & 3, prow = (bid >> 2) & 63, b = bid >> 8;
    for (int i = t; i < 64 * 64; i += 256) sM[(i >> 6) * 65 + (i & 63)] = d_M[i];
    if (t < 64) swf[t] = wfea[t];

    const char* gbase = (const char*)(fea + (size_t)b * 64 * HW * HW + (size_t)(prow * 8) * HW + xg * 128);
    uint32_t sbuf = cvta_smem(buf);

    auto load_chunk = [&](int chunk, int s) {
#pragma unroll
        for (int i = 0; i < 2; i++) {
            int id = t + i * 256;
            int ch = id >> 8, j = id & 255;
            int row = j >> 5, c = j & 31;
            cp16(sbuf + (s * 2048 + ch * 1024 + row * 128 + c * 4) * 4,
                 gbase + (size_t)(chunk * 2 + ch) * HW * HW * 4 + row * HW * 4 + c * 16);
        }
        asm volatile("cp.async.commit_group;" ::: "memory");
    };

    load_chunk(0, 0);
    load_chunk(1, 1);
    load_chunk(2, 2);

    int r = t >> 5, c4 = t & 31;
    float4 acc = {0.f, 0.f, 0.f, 0.f};

    for (int chunk = 0; chunk < 32; chunk++) {
        if (chunk + 3 < 32) load_chunk(chunk + 3, (chunk + 3) & 3);
        if (chunk + 3 < 32) { asm volatile("cp.async.wait_group 3;" ::: "memory"); }
        else if (chunk + 2 < 32) { asm volatile("cp.async.wait_group 2;" ::: "memory"); }
        else if (chunk + 1 < 32) { asm volatile("cp.async.wait_group 1;" ::: "memory"); }
        else { asm volatile("cp.async.wait_group 0;" ::: "memory"); }
        __syncthreads();
        const float* s = buf + (chunk & 3) * 2048;
#pragma unroll
        for (int ch = 0; ch < 2; ch++) {
            float4 v = *(const float4*)(s + ch * 1024 + r * 128 + c4 * 4);
            float w = swf[chunk * 2 + ch];
            acc.x += w * v.x; acc.y += w * v.y;
            acc.z += w * v.z; acc.w += w * v.w;
        }
        __syncthreads();
    }

    float bias = bfea[0];
    int colbase = c4 * 4;
    float* svp = &sv[(colbase >> 3) * 65 + r * 8 + (colbase & 7)];
    svp[0] = (acc.x + bias) * 0.25f;
    svp[1] = (acc.y + bias) * 0.25f;
    svp[2] = (acc.z + bias) * 0.25f;
    svp[3] = (acc.w + bias) * 0.25f;
    __syncthreads();

    int i = t & 63, pb = t >> 6;
    float s2[4] = {0.f, 0.f, 0.f, 0.f};
    for (int j = 0; j < 64; j++) {
        float mv = sM[i * 65 + j];
#pragma unroll
        for (int kk = 0; kk < 4; kk++) s2[kk] += mv * sv[(pb + 4 * kk) * 65 + j];
    }
#pragma unroll
    for (int kk = 0; kk < 4; kk++) {
        int p = pb + 4 * kk;
        int l = prow * 64 + xg * 16 + p;
        d_ufea[((size_t)b * LPATCH + l) * 64 + i] = __float2half_rn(fmaxf(s2[kk], 0.f));
    }
}

// ---------------- k3 body ----------------
#define LDMX4(d, a)                                                                     \
    asm volatile("ldmatrix.sync.aligned.m8n8.x4.shared.b16 {%0,%1,%2,%3}, [%4];"        \
                 : "=r"((d)[0]), "=r"((d)[1]), "=r"((d)[2]), "=r"((d)[3]) : "r"(a))

#define MMA_F16(d, a, bf)                                                               \
    asm volatile(                                                                       \
        "mma.sync.aligned.m16n8k16.row.col.f32.f16.f16.f32 "                            \
        "{%0,%1,%2,%3},{%4,%5,%6,%7},{%8,%9},{%0,%1,%2,%3};"                            \
        : "+f"((d)[0]), "+f"((d)[1]), "+f"((d)[2]), "+f"((d)[3])                        \
        : "r"((a)[0]), "r"((a)[1]), "r"((a)[2]), "r"((a)[3]), "r"((bf)[0]), "r"((bf)[1]))

#define ROWB 144
#define TILE_B (128 * ROWB)
#define K3_SMEM (3 * TILE_B)

__device__ __forceinline__ void k3_load_tile(uint32_t dst, const char* src, int t) {
#pragma unroll
    for (int i = 0; i < 4; i++) {
        int id = t + i * 256;
        int row = id >> 3, c = id & 7;
        cp16(dst + row * ROWB + c * 16, src + row * 128 + c * 16);
    }
}

__device__ void k3_body(float* __restrict__ att, int bm, int b, int hq, char* dsm) {
    uint32_t sbase = cvta_smem(dsm);
    int t = threadIdx.x;

    const char* Ag = (const char*)(d_uimg + ((size_t)b * LPATCH + bm * 128) * 64);
    const char* Bb = (const char*)(d_ufea + ((size_t)b * LPATCH + hq * 4 * 128) * 64);

    k3_load_tile(sbase, Ag, t);
    k3_load_tile(sbase + TILE_B, Bb, t);
    asm volatile("cp.async.commit_group;" ::: "memory");

    int warp = t >> 5, lane = t & 31;
    int wm = (warp >> 2) * 64;
    int wn = (warp & 3) * 32;
    int mat = lane >> 3, rr = lane & 7;
    int a_row = (mat & 1) * 8 + rr, a_col = (mat >> 1) * 8;
    int b_row = (mat >> 1) * 8 + rr, b_col = (mat & 1) * 8;
    int g = lane >> 2, tig = lane & 3;
    const float S = 1.f / 64.f;
    float* Cb = att + (size_t)b * LPATCH * LPATCH;

    for (int it = 0; it < 4; it++) {
        asm volatile("cp.async.wait_group 0;" ::: "memory");
        __syncthreads();
        if (it + 1 < 4) {
            k3_load_tile(sbase + TILE_B * (1 + ((it + 1) & 1)), Bb + (size_t)(it + 1) * 16384, t);
            asm volatile("cp.async.commit_group;" ::: "memory");
        }
        uint32_t boff = sbase + TILE_B * (1 + (it & 1));

        float acc[4][4][4];
#pragma unroll
        for (int mi = 0; mi < 4; mi++)
#pragma unroll
            for (int ni = 0; ni < 4; ni++)
#pragma unroll
                for (int q = 0; q < 4; q++) acc[mi][ni][q] = 0.f;

#pragma unroll
        for (int k = 0; k < 4; k++) {
            int k0 = k * 16;
            uint32_t bfr[4][2];
#pragma unroll
            for (int ni2 = 0; ni2 < 2; ni2++) {
                uint32_t tmp[4];
                uint32_t addr = boff + (wn + ni2 * 16 + b_row) * ROWB + (k0 + b_col) * 2;
                LDMX4(tmp, addr);
                bfr[ni2 * 2][0] = tmp[0]; bfr[ni2 * 2][1] = tmp[1];
                bfr[ni2 * 2 + 1][0] = tmp[2]; bfr[ni2 * 2 + 1][1] = tmp[3];
            }
            uint32_t afr[4][4];
#pragma unroll
            for (int mi = 0; mi < 4; mi++) {
                uint32_t addr = sbase + (wm + mi * 16 + a_row) * ROWB + (k0 + a_col) * 2;
                LDMX4(afr[mi], addr);
            }
#pragma unroll
            for (int mi = 0; mi < 4; mi++)
#pragma unroll
                for (int ni = 0; ni < 4; ni++) MMA_F16(acc[mi][ni], afr[mi], bfr[ni]);
        }

        int colq = (hq * 4 + it) * 128;
#pragma unroll
        for (int mi = 0; mi < 4; mi++)
#pragma unroll
            for (int ni = 0; ni < 4; ni++) {
                int row = bm * 128 + wm + mi * 16 + g;
                int colc = colq + wn + ni * 8 + tig * 2;
                float2 v0 = {acc[mi][ni][0] * S, acc[mi][ni][1] * S};
                float2 v1 = {acc[mi][ni][2] * S, acc[mi][ni][3] * S};
                __stcs((float2*)(Cb + (size_t)row * LPATCH + colc), v0);
                __stcs((float2*)(Cb + (size_t)(row + 8) * LPATCH + colc), v1);
            }
    }
}

// ---------------- phase kernels ----------------
#define K12_SMEM 53824
#define MIX_SMEM K3_SMEM   // 55296 >= K12_SMEM

// phase 1 / generic half of k12: 768 blocks, batches [2*half, 2*half+1]
__global__ void __launch_bounds__(256) k12_fused(const float* __restrict__ x,
                                                 const float* __restrict__ fea,
                                                 const float* __restrict__ wfea,
                                                 const float* __restrict__ bfea,
                                                 int half) {
    extern __shared__ __align__(128) float sm[];
    int id = blockIdx.x;
    if (id % 3 == 0) k1_body(x, half * 256 + id / 3, sm);
    else k2_body(fea, wfea, bfea, half * 512 + id - 1 - id / 3, sm);
}

// phase 2: mix of k12 half B (batches 2,3) and k3 half A (batches 0,1). 1280 blocks.
__global__ void __launch_bounds__(256, 2) k_mix(const float* __restrict__ x,
                                                const float* __restrict__ fea,
                                                const float* __restrict__ wfea,
                                                const float* __restrict__ bfea,
                                                float* __restrict__ att) {
    extern __shared__ __align__(128) char dsm[];
    int id = blockIdx.x;
    int grp = id / 5, rem = id % 5;
    if (rem < 3) {
        float* sm = (float*)dsm;
        if (rem == 0) k1_body(x, 256 + grp, sm);
        else k2_body(fea, wfea, bfea, 512 + 2 * grp + rem - 1, sm);
    } else {
        int m = grp * 2 + (rem - 3);            // 0..511
        k3_body(att, m & 31, (m >> 5) & 1, m >> 6, dsm);
    }
}

// phase 3: k3 half B (batches 2,3). 512 blocks.
__global__ void __launch_bounds__(256, 2) k3_half(float* __restrict__ att) {
    extern __shared__ __align__(128) char dsm[];
    int m = blockIdx.x;                          // 0..511
    k3_body(att, m & 31, 2 + ((m >> 5) & 1), m >> 6, dsm);
}

// ---------------- launch ----------------
extern "C" void kernel_launch(void* const* d_in, const int* in_sizes, int n_in,
                              void* d_out, int out_size) {
    const float* x    = (const float*)d_in[0];
    const float* fea  = (const float*)d_in[1];
    const float* wi1  = (const float*)d_in[2];
    const float* bi1  = (const float*)d_in[3];
    const float* wi2  = (const float*)d_in[4];
    const float* bi2  = (const float*)d_in[5];
    const float* wfea = (const float*)d_in[6];
    const float* bfea = (const float*)d_in[7];
    const float* w1   = (const float*)d_in[8];
    const float* w2   = (const float*)d_in[9];
    float* att = (float*)d_out;

    k0_compose<<<709, 256>>>(w1, w2, wi1, bi1, wi2, bi2);
    k1b_border<<<1024, 256>>>(x);
    cudaFuncSetAttribute(k12_fused, cudaFuncAttributeMaxDynamicSharedMemorySize, K12_SMEM);
    k12_fused<<<768, 256, K12_SMEM>>>(x, fea, wfea, bfea, 0);
    cudaFuncSetAttribute(k_mix, cudaFuncAttributeMaxDynamicSharedMemorySize, MIX_SMEM);
    k_mix<<<1280, 256, MIX_SMEM>>>(x, fea, wfea, bfea, att);
    cudaFuncSetAttribute(k3_half, cudaFuncAttributeMaxDynamicSharedMemorySize, K3_SMEM);
    k3_half<<<512, 256, K3_SMEM>>>(att);
}

// round 16
// speedup vs baseline: 1.1403x; 1.1403x over previous
#include <cuda_runtime.h>
#include <cuda_fp16.h>
#include <cstdint>

#define HW 512
#define LPATCH 4096

// ---------------- scratch ----------------
__device__ float d_M[64 * 64];
__device__ float d_wc[3 * 81];
__device__ float d_Wr[9 * 3 * 49];
__device__ float d_beta[9];
__device__ float d_bc;
__device__ float d_delta[4][4][512];
__device__ __align__(256) __half d_uimg[(size_t)4 * 4096 * 64];
__device__ __align__(256) __half d_ufea[(size_t)4 * 4096 * 64];

// ---------------- k0: compose weights, one WARP per output ----------------
__global__ void __launch_bounds__(256) k0_compose(
    const float* __restrict__ w1l, const float* __restrict__ w2l,
    const float* __restrict__ wi1, const float* __restrict__ bi1,
    const float* __restrict__ wi2, const float* __restrict__ bi2) {
    int w = (blockIdx.x * 256 + threadIdx.x) >> 5;
    int lane = threadIdx.x & 31;
    float sum = 0.f;
    if (w < 4096) {
        int i = w >> 6, j = w & 63;
#pragma unroll
        for (int k = lane; k < 128; k += 32) sum += w2l[i * 128 + k] * w1l[k * 64 + j];
#pragma unroll
        for (int o = 16; o; o >>= 1) sum += __shfl_xor_sync(0xFFFFFFFFu, sum, o);
        if (lane == 0) d_M[w] = sum;
    } else if (w < 4096 + 243) {
        int o = w - 4096;
        int c = o / 81, s = o % 81, sy = s / 9, sx = s % 9;
#pragma unroll
        for (int ry = 0; ry < 3; ry++)
#pragma unroll
            for (int rx = 0; rx < 3; rx++) {
                int qy = sy - ry, qx = sx - rx;
                if (qy < 0 || qy > 6 || qx < 0 || qx > 6) continue;
                for (int m = lane; m < 64; m += 32)
                    sum += wi2[m * 9 + ry * 3 + rx] * wi1[(m * 3 + c) * 49 + qy * 7 + qx];
            }
#pragma unroll
        for (int o2 = 16; o2; o2 >>= 1) sum += __shfl_xor_sync(0xFFFFFFFFu, sum, o2);
        if (lane == 0) d_wc[o] = sum;
    } else if (w < 4096 + 243 + 1323) {
        int o = w - 4096 - 243;
        int r = o / 147, rem = o % 147, c = rem / 49, q = rem % 49;
        for (int m = lane; m < 64; m += 32)
            sum += wi2[m * 9 + r] * wi1[(m * 3 + c) * 49 + q];
#pragma unroll
        for (int o2 = 16; o2; o2 >>= 1) sum += __shfl_xor_sync(0xFFFFFFFFu, sum, o2);
        if (lane == 0) d_Wr[o] = sum;
    } else if (w == 4096 + 243 + 1323) {
#pragma unroll
        for (int r = 0; r < 9; r++) {
            float s2 = 0.f;
            for (int m = lane; m < 64; m += 32) s2 += wi2[m * 9 + r] * bi1[m];
#pragma unroll
            for (int o2 = 16; o2; o2 >>= 1) s2 += __shfl_xor_sync(0xFFFFFFFFu, s2, o2);
            if (lane == 0) d_beta[r] = s2;
        }
    } else if (w == 4096 + 243 + 1323 + 1) {
        float s2 = 0.f;
        for (int m = lane; m < 64; m += 32) {
            float sw = 0.f;
#pragma unroll
            for (int r = 0; r < 9; r++) sw += wi2[m * 9 + r];
            s2 += bi1[m] * sw;
        }
#pragma unroll
        for (int o2 = 16; o2; o2 >>= 1) s2 += __shfl_xor_sync(0xFFFFFFFFu, s2, o2);
        if (lane == 0) d_bc = s2 + bi2[0];
    }
}

// ---------------- k1b: border deltas, one WARP per border pixel ----------------
__global__ void __launch_bounds__(256) k1b_border(const float* __restrict__ x) {
    int wid_g = (blockIdx.x * 256 + threadIdx.x) >> 5;
    int lane = threadIdx.x & 31;
    int b = wid_g >> 11, rem = wid_g & 2047, edge = rem >> 9, idx = rem & 511;
    int oy, ox;
    if (edge == 0) { oy = 0;   ox = idx; }
    else if (edge == 1) { oy = 511; ox = idx; }
    else if (edge == 2) { oy = idx; ox = 0; }
    else { oy = idx; ox = 511; }
    const float* xb = x + (size_t)b * 3 * HW * HW;
    float sum = 0.f;
#pragma unroll
    for (int ry = 0; ry < 3; ry++)
#pragma unroll
        for (int rx = 0; rx < 3; rx++) {
            int py = oy + ry - 1, px = ox + rx - 1;
            if (py >= 0 && py < HW && px >= 0 && px < HW) continue;
            int r = ry * 3 + rx;
            if (lane == 0) sum += d_beta[r];
            for (int e = lane; e < 147; e += 32) {
                int c = e / 49, q = e % 49, qy = q / 7, qx = q % 7;
                int gy = py + qy - 3, gx = px + qx - 3;
                if (gy >= 0 && gy < HW && gx >= 0 && gx < HW)
                    sum += d_Wr[(r * 3 + c) * 49 + q] * xb[c * HW * HW + gy * HW + gx];
            }
        }
#pragma unroll
    for (int o = 16; o; o >>= 1) sum += __shfl_xor_sync(0xFFFFFFFFu, sum, o);
    if (lane == 0) d_delta[b][edge][idx] = -sum;
}

// ---------------- helpers ----------------
__device__ __forceinline__ uint32_t cvta_smem(const void* p) {
    uint32_t a;
    asm("{ .reg .u64 t; cvta.to.shared.u64 t, %1; cvt.u32.u64 %0, t; }" : "=r"(a) : "l"(p));
    return a;
}
__device__ __forceinline__ void cp16(uint32_t dst, const void* src) {
    asm volatile("cp.async.cg.shared.global [%0], [%1], 16;" :: "r"(dst), "l"(src));
}

// ---------------- fused k1 (conv path) + k2 (fea path), dispatch on blockIdx ----------------
__device__ void k1_body(const float* __restrict__ x, int bid, float* sm) {
    float* sxc = sm;
    float* swc = sm + 2880;
    float* sM  = sm + 2880 + 256;
    float* sv  = sm + 2880 + 256 + 4160;
    int t = threadIdx.x;
    int xg = bid & 7, yg = (bid >> 3) & 15, b = bid >> 7;
    int ix0 = xg * 64, iy0 = yg * 32;
    const float* xb = x + (size_t)b * 3 * HW * HW;

    for (int i = t; i < 3 * 81; i += 256) swc[i] = d_wc[i];
    for (int i = t; i < 64 * 64; i += 256) sM[(i >> 6) * 65 + (i & 63)] = d_M[i];

    int col = t & 63, rg = t >> 6;
    float acc[8];
    float bias = d_bc;
#pragma unroll
    for (int j = 0; j < 8; j++) acc[j] = bias;

    for (int c = 0; c < 3; c++) {
        __syncthreads();
        for (int i = t; i < 2880; i += 256) {
            int r = i / 72, cc = i % 72;
            int gy = iy0 - 4 + r, gx = ix0 - 4 + cc;
            sxc[i] = (gy >= 0 && gy < HW && gx >= 0 && gx < HW) ? xb[c * HW * HW + gy * HW + gx] : 0.f;
        }
        __syncthreads();
#pragma unroll
        for (int dx = 0; dx < 9; dx++) {
            float win[16];
#pragma unroll
            for (int u = 0; u < 16; u++) win[u] = sxc[(rg * 8 + u) * 72 + col + dx];
#pragma unroll
            for (int dy = 0; dy < 9; dy++) {
                float w = swc[c * 81 + dy * 9 + dx];
#pragma unroll
                for (int j = 0; j < 8; j++) acc[j] += w * win[j + dy];
            }
        }
    }

    int oybase = iy0 + rg * 8;
    int ox = ix0 + col;
#pragma unroll
    for (int j = 0; j < 8; j++) {
        int oy = oybase + j;
        float a = acc[j];
        if (oy == 0) a += d_delta[b][0][ox];
        if (oy == 511) a += d_delta[b][1][ox];
        if (ox == 0 && oy > 0 && oy < 511) a += d_delta[b][2][oy];
        if (ox == 511 && oy > 0 && oy < 511) a += d_delta[b][3][oy];
        sv[(rg * 8 + (col >> 3)) * 65 + j * 8 + (col & 7)] = a;
    }
    __syncthreads();

    int i = t & 63, pb = t >> 6;
    float s[8];
#pragma unroll
    for (int kk = 0; kk < 8; kk++) s[kk] = 0.f;
    for (int j = 0; j < 64; j++) {
        float mv = sM[i * 65 + j];
#pragma unroll
        for (int kk = 0; kk < 8; kk++) s[kk] += mv * sv[(pb + 4 * kk) * 65 + j];
    }
    int prow0 = iy0 >> 3, pcol0 = ix0 >> 3;
#pragma unroll
    for (int kk = 0; kk < 8; kk++) {
        int p = pb + 4 * kk;
        int l = (prow0 + (p >> 3)) * 64 + pcol0 + (p & 7);
        d_uimg[((size_t)b * LPATCH + l) * 64 + i] = __float2half_rn(fmaxf(s[kk], 0.f));
    }
}

__device__ void k2_body(const float* __restrict__ fea, const float* __restrict__ wfea,
                        const float* __restrict__ bfea, int bid, float* sm) {
    float* buf = sm;
    float* sM  = sm + 8192;
    float* sv  = sm + 8192 + 4160;
    float* swf = sm + 8192 + 4160 + 1040;
    int t = threadIdx.x;
    int xg = bid & 3, prow = (bid >> 2) & 63, b = bid >> 8;
    for (int i = t; i < 64 * 64; i += 256) sM[(i >> 6) * 65 + (i & 63)] = d_M[i];
    if (t < 64) swf[t] = wfea[t];

    const char* gbase = (const char*)(fea + (size_t)b * 64 * HW * HW + (size_t)(prow * 8) * HW + xg * 128);
    uint32_t sbuf = cvta_smem(buf);

    auto load_chunk = [&](int chunk, int s) {
#pragma unroll
        for (int i = 0; i < 2; i++) {
            int id = t + i * 256;
            int ch = id >> 8, j = id & 255;
            int row = j >> 5, c = j & 31;
            cp16(sbuf + (s * 2048 + ch * 1024 + row * 128 + c * 4) * 4,
                 gbase + (size_t)(chunk * 2 + ch) * HW * HW * 4 + row * HW * 4 + c * 16);
        }
        asm volatile("cp.async.commit_group;" ::: "memory");
    };

    load_chunk(0, 0);
    load_chunk(1, 1);
    load_chunk(2, 2);

    int r = t >> 5, c4 = t & 31;
    float4 acc = {0.f, 0.f, 0.f, 0.f};

    for (int chunk = 0; chunk < 32; chunk++) {
        if (chunk + 3 < 32) load_chunk(chunk + 3, (chunk + 3) & 3);
        if (chunk + 3 < 32) { asm volatile("cp.async.wait_group 3;" ::: "memory"); }
        else if (chunk + 2 < 32) { asm volatile("cp.async.wait_group 2;" ::: "memory"); }
        else if (chunk + 1 < 32) { asm volatile("cp.async.wait_group 1;" ::: "memory"); }
        else { asm volatile("cp.async.wait_group 0;" ::: "memory"); }
        __syncthreads();
        const float* s = buf + (chunk & 3) * 2048;
#pragma unroll
        for (int ch = 0; ch < 2; ch++) {
            float4 v = *(const float4*)(s + ch * 1024 + r * 128 + c4 * 4);
            float w = swf[chunk * 2 + ch];
            acc.x += w * v.x; acc.y += w * v.y;
            acc.z += w * v.z; acc.w += w * v.w;
        }
        __syncthreads();
    }

    float bias = bfea[0];
    int colbase = c4 * 4;
    float* svp = &sv[(colbase >> 3) * 65 + r * 8 + (colbase & 7)];
    svp[0] = (acc.x + bias) * 0.25f;
    svp[1] = (acc.y + bias) * 0.25f;
    svp[2] = (acc.z + bias) * 0.25f;
    svp[3] = (acc.w + bias) * 0.25f;
    __syncthreads();

    int i = t & 63, pb = t >> 6;
    float s2[4] = {0.f, 0.f, 0.f, 0.f};
    for (int j = 0; j < 64; j++) {
        float mv = sM[i * 65 + j];
#pragma unroll
        for (int kk = 0; kk < 4; kk++) s2[kk] += mv * sv[(pb + 4 * kk) * 65 + j];
    }
#pragma unroll
    for (int kk = 0; kk < 4; kk++) {
        int p = pb + 4 * kk;
        int l = prow * 64 + xg * 16 + p;
        d_ufea[((size_t)b * LPATCH + l) * 64 + i] = __float2half_rn(fmaxf(s2[kk], 0.f));
    }
}

__global__ void __launch_bounds__(256) k12_fused(const float* __restrict__ x,
                                                 const float* __restrict__ fea,
                                                 const float* __restrict__ wfea,
                                                 const float* __restrict__ bfea) {
    extern __shared__ __align__(16) float sm[];
    int id = blockIdx.x;            // 0..1535; every 3rd block is a k1 block
    if (id % 3 == 0) k1_body(x, id / 3, sm);
    else k2_body(fea, wfea, bfea, id - 1 - id / 3, sm);
}
#define K12_SMEM 53824

// ================= k3: fp16 mma.sync GEMM, A-resident, pipelined B, streaming stores =================
#define LDMX4(d, a)                                                                     \
    asm volatile("ldmatrix.sync.aligned.m8n8.x4.shared.b16 {%0,%1,%2,%3}, [%4];"        \
                 : "=r"((d)[0]), "=r"((d)[1]), "=r"((d)[2]), "=r"((d)[3]) : "r"(a))

#define MMA_F16(d, a, bf)                                                               \
    asm volatile(                                                                       \
        "mma.sync.aligned.m16n8k16.row.col.f32.f16.f16.f32 "                            \
        "{%0,%1,%2,%3},{%4,%5,%6,%7},{%8,%9},{%0,%1,%2,%3};"                            \
        : "+f"((d)[0]), "+f"((d)[1]), "+f"((d)[2]), "+f"((d)[3])                        \
        : "r"((a)[0]), "r"((a)[1]), "r"((a)[2]), "r"((a)[3]), "r"((bf)[0]), "r"((bf)[1]))

#define ROWB 144
#define TILE_B (128 * ROWB)
#define K3_SMEM (3 * TILE_B)

__device__ __forceinline__ void k3_load_tile(uint32_t dst, const char* src, int t) {
#pragma unroll
    for (int i = 0; i < 4; i++) {
        int id = t + i * 256;
        int row = id >> 3, c = id & 7;
        cp16(dst + row * ROWB + c * 16, src + row * 128 + c * 16);
    }
}

__global__ void __launch_bounds__(256, 2) k3_gemm(float* __restrict__ att) {
    extern __shared__ __align__(128) char dsm[];
    uint32_t sbase = cvta_smem(dsm);
    int t = threadIdx.x;
    int bm = blockIdx.x, b = blockIdx.y, hq = blockIdx.z;

    const char* Ag = (const char*)(d_uimg + ((size_t)b * LPATCH + bm * 128) * 64);
    const char* Bb = (const char*)(d_ufea + ((size_t)b * LPATCH + hq * 4 * 128) * 64);

    k3_load_tile(sbase, Ag, t);
    k3_load_tile(sbase + TILE_B, Bb, t);
    asm volatile("cp.async.commit_group;" ::: "memory");

    int warp = t >> 5, lane = t & 31;
    int wm = (warp >> 2) * 64;
    int wn = (warp & 3) * 32;
    int mat = lane >> 3, rr = lane & 7;
    int a_row = (mat & 1) * 8 + rr, a_col = (mat >> 1) * 8;
    int b_row = (mat >> 1) * 8 + rr, b_col = (mat & 1) * 8;
    int g = lane >> 2, tig = lane & 3;
    const float S = 1.f / 64.f;
    float* Cb = att + (size_t)b * LPATCH * LPATCH;

    for (int it = 0; it < 4; it++) {
        asm volatile("cp.async.wait_group 0;" ::: "memory");
        __syncthreads();
        if (it + 1 < 4) {
            k3_load_tile(sbase + TILE_B * (1 + ((it + 1) & 1)), Bb + (size_t)(it + 1) * 16384, t);
            asm volatile("cp.async.commit_group;" ::: "memory");
        }
        uint32_t boff = sbase + TILE_B * (1 + (it & 1));

        float acc[4][4][4];
#pragma unroll
        for (int mi = 0; mi < 4; mi++)
#pragma unroll
            for (int ni = 0; ni < 4; ni++)
#pragma unroll
                for (int q = 0; q < 4; q++) acc[mi][ni][q] = 0.f;

#pragma unroll
        for (int k = 0; k < 4; k++) {
            int k0 = k * 16;
            uint32_t bfr[4][2];
#pragma unroll
            for (int ni2 = 0; ni2 < 2; ni2++) {
                uint32_t tmp[4];
                uint32_t addr = boff + (wn + ni2 * 16 + b_row) * ROWB + (k0 + b_col) * 2;
                LDMX4(tmp, addr);
                bfr[ni2 * 2][0] = tmp[0]; bfr[ni2 * 2][1] = tmp[1];
                bfr[ni2 * 2 + 1][0] = tmp[2]; bfr[ni2 * 2 + 1][1] = tmp[3];
            }
            uint32_t afr[4][4];
#pragma unroll
            for (int mi = 0; mi < 4; mi++) {
                uint32_t addr = sbase + (wm + mi * 16 + a_row) * ROWB + (k0 + a_col) * 2;
                LDMX4(afr[mi], addr);
            }
#pragma unroll
            for (int mi = 0; mi < 4; mi++)
#pragma unroll
                for (int ni = 0; ni < 4; ni++) MMA_F16(acc[mi][ni], afr[mi], bfr[ni]);
        }

        int colq = (hq * 4 + it) * 128;
#pragma unroll
        for (int mi = 0; mi < 4; mi++)
#pragma unroll
            for (int ni = 0; ni < 4; ni++) {
                int row = bm * 128 + wm + mi * 16 + g;
                int colc = colq + wn + ni * 8 + tig * 2;
                float2 v0 = {acc[mi][ni][0] * S, acc[mi][ni][1] * S};
                float2 v1 = {acc[mi][ni][2] * S, acc[mi][ni][3] * S};
                __stcs((float2*)(Cb + (size_t)row * LPATCH + colc), v0);
                __stcs((float2*)(Cb + (size_t)(row + 8) * LPATCH + colc), v1);
            }
    }
}

// ---------------- launch ----------------
extern "C" void kernel_launch(void* const* d_in, const int* in_sizes, int n_in,
                              void* d_out, int out_size) {
    const float* x    = (const float*)d_in[0];
    const float* fea  = (const float*)d_in[1];
    const float* wi1  = (const float*)d_in[2];
    const float* bi1  = (const float*)d_in[3];
    const float* wi2  = (const float*)d_in[4];
    const float* bi2  = (const float*)d_in[5];
    const float* wfea = (const float*)d_in[6];
    const float* bfea = (const float*)d_in[7];
    const float* w1   = (const float*)d_in[8];
    const float* w2   = (const float*)d_in[9];
    float* att = (float*)d_out;

    k0_compose<<<709, 256>>>(w1, w2, wi1, bi1, wi2, bi2);
    k1b_border<<<1024, 256>>>(x);
    cudaFuncSetAttribute(k12_fused, cudaFuncAttributeMaxDynamicSharedMemorySize, K12_SMEM);
    k12_fused<<<1536, 256, K12_SMEM>>>(x, fea, wfea, bfea);
    cudaFuncSetAttribute(k3_gemm, cudaFuncAttributeMaxDynamicSharedMemorySize, K3_SMEM);
    k3_gemm<<<dim3(32, 4, 8), 256, K3_SMEM>>>(att);
}